// round 2
// baseline (speedup 1.0000x reference)
#include <cuda_runtime.h>
#include <cstring>
#include <cstdint>

// ---------------- problem constants ----------------
#define HEADS   24
#define HDIM    128
#define NQB     54      // q blocks: grid (3,3,6) over canvas (12,24,48)/tile(4,8,8)
#define NKVB    120     // kv blocks: grid (3,5,8) over glued canvas (12,40,64)
#define BSZ     256     // tokens per block (4*8*8)
#define LQ      13824
#define SOFT_SCALE 0.08838834764831845f          // 1/sqrt(128)
#define LOG2E      1.4426950408889634f

// ---------------- scratch (device globals; no cudaMalloc allowed) ----------
__device__ float g_Qp[(size_t)HEADS*NQB*BSZ*HDIM];    // [h][qb][t][e], rope'd, scaled by SOFT_SCALE*LOG2E
__device__ float g_Kp[(size_t)HEADS*NKVB*BSZ*HDIM];   // [h][kb][t][e], glued + rope'd
__device__ float g_Vp[(size_t)HEADS*NKVB*BSZ*HDIM];   // [h][kb][t][e], glued

// ---------------- helpers ----------------
__device__ __forceinline__ void ffma2(float2& d, float2 a, float2 b) {
    unsigned long long da, db, dd;
    memcpy(&da, &a, 8); memcpy(&db, &b, 8); memcpy(&dd, &d, 8);
    asm("fma.rn.f32x2 %0, %1, %2, %0;" : "+l"(dd) : "l"(da), "l"(db));
    memcpy(&d, &dd, 8);
}
__device__ __forceinline__ float fast_exp2(float x) {
    float y; asm("ex2.approx.ftz.f32 %0, %1;" : "=f"(y) : "f"(x)); return y;
}
__device__ __forceinline__ float warp_max16(float v) {
    #pragma unroll
    for (int k = 1; k < 16; k <<= 1) v = fmaxf(v, __shfl_xor_sync(0xffffffffu, v, k));
    return v;
}
__device__ __forceinline__ float warp_sum16(float v) {
    #pragma unroll
    for (int k = 1; k < 16; k <<= 1) v += __shfl_xor_sync(0xffffffffu, v, k);
    return v;
}

// RoPE for channel pair p (p = e/2, 0..63). dims (16,56,56) over axes T,H,W.
// freqs = theta^(-2i/dim) = 2^(-16 i/dim) for theta=256.
__device__ __forceinline__ void rope_pair(int p, int posT, int posH, int posW,
                                          float x0, float x1, float sc,
                                          float& o0, float& o1) {
    float fi, fdim, pp;
    if (p < 8)       { fi = (float)p;        fdim = 16.0f; pp = (float)posT; }
    else if (p < 36) { fi = (float)(p - 8);  fdim = 56.0f; pp = (float)posH; }
    else             { fi = (float)(p - 36); fdim = 56.0f; pp = (float)posW; }
    float freq = exp2f(-16.0f * fi / fdim);
    float ang = pp * freq;
    float s, c;
    sincosf(ang, &s, &c);
    o0 = (x0 * c - x1 * s) * sc;
    o1 = (x1 * c + x0 * s) * sc;
}

// ---------------- prep kernels ----------------
// Q: one thread per channel pair. idx = ((h*54+qb)*256+t)*64 + p
__global__ void prep_q_kernel(const float* __restrict__ qin) {
    int idx = blockIdx.x * blockDim.x + threadIdx.x;
    if (idx >= HEADS * NQB * BSZ * 64) return;
    int p  = idx & 63;
    int t  = (idx >> 6) & 255;
    int r  = idx >> 14;
    int qb = r % NQB;
    int h  = r / NQB;
    int qt = qb / 18, qh = (qb / 6) % 3, qw = qb % 6;
    int t0 = t >> 6, t1 = (t >> 3) & 7, t2 = t & 7;
    int Tc = qt * 4 + t0, Hc = qh * 8 + t1, Wc = qw * 8 + t2;
    int pos = (Tc * 24 + Hc) * 48 + Wc;
    float2 x = *(const float2*)(qin + ((size_t)pos * HEADS + h) * HDIM + 2 * p);
    float o0, o1;
    rope_pair(p, Tc, Hc, Wc, x.x, x.y, SOFT_SCALE * LOG2E, o0, o1);
    *(float2*)(g_Qp + (size_t)idx * 2) = make_float2(o0, o1);
}

// K: glued canvas, wrap source, negative positions for rope on padded dims.
__global__ void prep_k_kernel(const float* __restrict__ kin) {
    int idx = blockIdx.x * blockDim.x + threadIdx.x;
    if (idx >= HEADS * NKVB * BSZ * 64) return;
    int p  = idx & 63;
    int t  = (idx >> 6) & 255;
    int r  = idx >> 14;
    int kb = r % NKVB;
    int h  = r / NKVB;
    int kt = kb / 40, kh = (kb >> 3) % 5, kw = kb & 7;
    int t0 = t >> 6, t1 = (t >> 3) & 7, t2 = t & 7;
    int Tg = kt * 4 + t0;            // 0..11 (no pad on T)
    int Hg = kh * 8 + t1;            // 0..39
    int Wg = kw * 8 + t2;            // 0..63
    int Hc = (Hg + 16) % 24;         // (Hg-8) mod 24 wrap
    int Wc = (Wg + 40) % 48;         // (Wg-8) mod 48 wrap
    int pos = (Tg * 24 + Hc) * 48 + Wc;
    float2 x = *(const float2*)(kin + ((size_t)pos * HEADS + h) * HDIM + 2 * p);
    float o0, o1;
    rope_pair(p, Tg, Hg - 8, Wg - 8, x.x, x.y, 1.0f, o0, o1);
    *(float2*)(g_Kp + (size_t)idx * 2) = make_float2(o0, o1);
}

// V: glued copy, no rope. one thread per float4.
__global__ void prep_v_kernel(const float* __restrict__ vin) {
    int idx = blockIdx.x * blockDim.x + threadIdx.x;
    if (idx >= HEADS * NKVB * BSZ * 32) return;
    int e4 = idx & 31;
    int t  = (idx >> 5) & 255;
    int r  = idx >> 13;
    int kb = r % NKVB;
    int h  = r / NKVB;
    int kt = kb / 40, kh = (kb >> 3) % 5, kw = kb & 7;
    int t0 = t >> 6, t1 = (t >> 3) & 7, t2 = t & 7;
    int Tg = kt * 4 + t0;
    int Hc = (kh * 8 + t1 + 16) % 24;
    int Wc = (kw * 8 + t2 + 40) % 48;
    int pos = (Tg * 24 + Hc) * 48 + Wc;
    float4 x = *(const float4*)(vin + ((size_t)pos * HEADS + h) * HDIM + e4 * 4);
    *(float4*)(g_Vp + (size_t)idx * 4) = x;
}

// ---------------- attention kernel ----------------
// CTA = (h, half, qb): 128 q rows. 8 warps x 16 rows.
// lane = lr*16+lc, lr in {0,1}, lc in [0,16). Thread: rows rb..rb+7 (rb=w*16+lr*8),
// cols/dims n*16+lc (n<8). Pairs over rows (f32x2), dup over cols.
#define STR 130      // smem row stride (floats) for Qt / KtP
#define SMEM_FLOATS (2*128*STR + 128*128)

__global__ void __launch_bounds__(256, 1)
attn_kernel(float* __restrict__ out) {
    extern __shared__ float sm[];
    float*  Qt  = sm;                     // [d:128][row:128] stride STR
    float*  KtP = sm + 128 * STR;         // Kt: [d][kv j]  /  Ps: [kv j][row]
    float*  Vs  = sm + 2 * 128 * STR;     // [j:128][e:128]

    int bx = blockIdx.x;
    int h    = bx / 108;
    int rem  = bx % 108;
    int half = rem / NQB;
    int qb   = rem % NQB;
    int qt = qb / 18, qh = (qb / 6) % 3, qw = qb % 6;

    int tid = threadIdx.x;
    int w = tid >> 5, lane = tid & 31;
    int lr = lane >> 4, lc = lane & 15;
    int rb = w * 16 + lr * 8;

    // ---- load Q tile (128 rows x 128 dims), transposed into Qt[d][row] ----
    const float4* qg = (const float4*)(g_Qp + (((size_t)h * NQB + qb) * BSZ + half * 128) * HDIM);
    #pragma unroll
    for (int i = 0; i < 16; i++) {
        int ii = i * 256 + tid;
        int tt = ii >> 5, e4 = ii & 31;
        float4 v = qg[ii];
        float* dst = Qt + (e4 * 4) * STR + tt;
        dst[0] = v.x; dst[STR] = v.y; dst[2 * STR] = v.z; dst[3 * STR] = v.w;
    }

    float2 s2[4][8], o2[4][8];
    float mi[8], li[8];
    #pragma unroll
    for (int m = 0; m < 4; m++)
        #pragma unroll
        for (int n = 0; n < 8; n++) o2[m][n] = make_float2(0.f, 0.f);
    #pragma unroll
    for (int r = 0; r < 8; r++) { mi[r] = -1e30f; li[r] = 0.f; }

    for (int ci = 0; ci < 54; ci++) {
        int bi = ci >> 1;
        int toff = (ci & 1) << 7;
        int kb = (bi / 9) * 40 + (qh + (bi / 3) % 3) * 8 + (qw + bi % 3);
        const float4* kg = (const float4*)(g_Kp + (((size_t)h * NKVB + kb) * BSZ + toff) * HDIM);
        const float4* vg = (const float4*)(g_Vp + (((size_t)h * NKVB + kb) * BSZ + toff) * HDIM);

        __syncthreads();   // previous iteration's Ps reads complete
        #pragma unroll
        for (int i = 0; i < 16; i++) {
            int ii = i * 256 + tid;
            int tt = ii >> 5, e4 = ii & 31;
            float4 v = kg[ii];
            float* dst = KtP + (e4 * 4) * STR + tt;    // Kt[d][j]
            dst[0] = v.x; dst[STR] = v.y; dst[2 * STR] = v.z; dst[3 * STR] = v.w;
            ((float4*)Vs)[ii] = vg[ii];                // V[j][e] flat
        }
        __syncthreads();

        // ---- S = Q K^T (rows x 128 kv chunk) ----
        #pragma unroll
        for (int m = 0; m < 4; m++)
            #pragma unroll
            for (int n = 0; n < 8; n++) s2[m][n] = make_float2(0.f, 0.f);

        #pragma unroll 2
        for (int d = 0; d < 128; d++) {
            const float* qrow = Qt + d * STR + rb;
            float2 q2[4];
            #pragma unroll
            for (int m = 0; m < 4; m++) q2[m] = *(const float2*)(qrow + 2 * m);
            const float* krow = KtP + d * STR + lc;
            #pragma unroll
            for (int n = 0; n < 8; n++) {
                float kv = krow[n * 16];
                float2 kd = make_float2(kv, kv);
                #pragma unroll
                for (int m = 0; m < 4; m++) ffma2(s2[m][n], q2[m], kd);
            }
        }

        // ---- online softmax (per row); p values left in s2 ----
        #pragma unroll
        for (int m = 0; m < 4; m++) {
            float ax = -1e30f, ay = -1e30f;
            #pragma unroll
            for (int n = 0; n < 8; n++) { ax = fmaxf(ax, s2[m][n].x); ay = fmaxf(ay, s2[m][n].y); }
            ax = warp_max16(ax); ay = warp_max16(ay);
            float mx = fmaxf(mi[2 * m], ax), my = fmaxf(mi[2 * m + 1], ay);
            float cx = fast_exp2(mi[2 * m] - mx), cy = fast_exp2(mi[2 * m + 1] - my);
            float sx = 0.f, sy = 0.f;
            #pragma unroll
            for (int n = 0; n < 8; n++) {
                float ex = fast_exp2(s2[m][n].x - mx);
                float ey = fast_exp2(s2[m][n].y - my);
                s2[m][n] = make_float2(ex, ey);
                sx += ex; sy += ey;
            }
            sx = warp_sum16(sx); sy = warp_sum16(sy);
            li[2 * m]     = li[2 * m]     * cx + sx;
            li[2 * m + 1] = li[2 * m + 1] * cy + sy;
            mi[2 * m] = mx; mi[2 * m + 1] = my;
            #pragma unroll
            for (int n = 0; n < 8; n++) { o2[m][n].x *= cx; o2[m][n].y *= cy; }
        }

        __syncthreads();   // everyone done reading Kt before overwriting with Ps
        #pragma unroll
        for (int n = 0; n < 8; n++)
            #pragma unroll
            for (int m = 0; m < 4; m++)
                *(float2*)(KtP + (n * 16 + lc) * STR + rb + 2 * m) = s2[m][n];
        __syncwarp();      // warp reads only its own row range of Ps

        // ---- O += P V ----
        #pragma unroll 2
        for (int j = 0; j < 128; j++) {
            const float* prow = KtP + j * STR + rb;
            float2 p2[4];
            #pragma unroll
            for (int m = 0; m < 4; m++) p2[m] = *(const float2*)(prow + 2 * m);
            const float* vrow = Vs + j * 128 + lc;
            #pragma unroll
            for (int n = 0; n < 8; n++) {
                float vv = vrow[n * 16];
                float2 vd = make_float2(vv, vv);
                #pragma unroll
                for (int m = 0; m < 4; m++) ffma2(o2[m][n], p2[m], vd);
            }
        }
    }

    // ---- epilogue: divide by l, untile, write ----
    #pragma unroll
    for (int m = 0; m < 4; m++) {
        float inv0 = 1.0f / li[2 * m];
        float inv1 = 1.0f / li[2 * m + 1];
        int tloc = half * 128 + rb + 2 * m;
        #pragma unroll
        for (int rr = 0; rr < 2; rr++) {
            int t = tloc + rr;
            float inv = rr ? inv1 : inv0;
            int t0 = t >> 6, t1 = (t >> 3) & 7, t2 = t & 7;
            int pos = ((qt * 4 + t0) * 24 + qh * 8 + t1) * 48 + (qw * 8 + t2);
            float* ob = out + ((size_t)pos * HEADS + h) * HDIM;
            #pragma unroll
            for (int n = 0; n < 8; n++) {
                float v = rr ? o2[m][n].y : o2[m][n].x;
                ob[n * 16 + lc] = v * inv;
            }
        }
    }
}

// ---------------- launch ----------------
extern "C" void kernel_launch(void* const* d_in, const int* in_sizes, int n_in,
                              void* d_out, int out_size) {
    const float* q = (const float*)d_in[0];
    const float* k = (const float*)d_in[1];
    const float* v = (const float*)d_in[2];
    float* out = (float*)d_out;

    prep_q_kernel<<<(HEADS * NQB * BSZ * 64) / 256, 256>>>(q);
    prep_k_kernel<<<(HEADS * NKVB * BSZ * 64) / 256, 256>>>(k);
    prep_v_kernel<<<(HEADS * NKVB * BSZ * 32) / 256, 256>>>(v);

    size_t smem = SMEM_FLOATS * sizeof(float);   // 198,656 B
    cudaFuncSetAttribute(attn_kernel, cudaFuncAttributeMaxDynamicSharedMemorySize, (int)smem);
    attn_kernel<<<HEADS * 2 * NQB, 256, smem>>>(out);
}

// round 10
// speedup vs baseline: 2.1657x; 2.1657x over previous
#include <cuda_runtime.h>
#include <cuda_bf16.h>
#include <cstdint>

// ---------------- problem constants ----------------
#define HEADS   24
#define HDIM    128
#define NQB     54
#define NKVB    120
#define BSZ     256
#define NCH     108                       // 27 blocks * 4 chunks of 64
#define QK_SCALE 0.127517443f             // (1/sqrt(128)) * log2(e), folded into Q

typedef __nv_bfloat16 bf16;

// ---------------- scratch (device globals; no cudaMalloc allowed) ----------
__device__ bf16 g_Qhi[(size_t)HEADS*NQB*BSZ*HDIM];    // [h][qb][t][e]
__device__ bf16 g_Qlo[(size_t)HEADS*NQB*BSZ*HDIM];
__device__ bf16 g_Khi[(size_t)HEADS*NKVB*BSZ*HDIM];   // [h][kb][t][e]
__device__ bf16 g_Klo[(size_t)HEADS*NKVB*BSZ*HDIM];
__device__ bf16 g_Vhi[(size_t)HEADS*NKVB*BSZ*HDIM];   // [h][kb][t][e] (no transpose)
__device__ bf16 g_Vlo[(size_t)HEADS*NKVB*BSZ*HDIM];

// ---------------- PTX helpers (baseline ISA only: sm_80-class) -------------
__device__ __forceinline__ uint32_t smem_u32(const void* p) {
    uint32_t a;
    asm("{ .reg .u64 t; cvta.to.shared.u64 t, %1; cvt.u32.u64 %0, t; }" : "=r"(a) : "l"(p));
    return a;
}
__device__ __forceinline__ float fast_exp2(float x) {
    float y; asm("ex2.approx.ftz.f32 %0, %1;" : "=f"(y) : "f"(x)); return y;
}
__device__ __forceinline__ void ldsm4(uint32_t r[4], uint32_t a) {
    asm volatile("ldmatrix.sync.aligned.m8n8.x4.shared.b16 {%0,%1,%2,%3}, [%4];"
        : "=r"(r[0]), "=r"(r[1]), "=r"(r[2]), "=r"(r[3]) : "r"(a));
}
__device__ __forceinline__ void ldsm4t(uint32_t r[4], uint32_t a) {
    asm volatile("ldmatrix.sync.aligned.m8n8.x4.trans.shared.b16 {%0,%1,%2,%3}, [%4];"
        : "=r"(r[0]), "=r"(r[1]), "=r"(r[2]), "=r"(r[3]) : "r"(a));
}
__device__ __forceinline__ void mma_bf(float c[4], const uint32_t a[4], uint32_t b0, uint32_t b1) {
    asm volatile("mma.sync.aligned.m16n8k16.row.col.f32.bf16.bf16.f32 "
        "{%0,%1,%2,%3}, {%4,%5,%6,%7}, {%8,%9}, {%0,%1,%2,%3};"
        : "+f"(c[0]), "+f"(c[1]), "+f"(c[2]), "+f"(c[3])
        : "r"(a[0]), "r"(a[1]), "r"(a[2]), "r"(a[3]), "r"(b0), "r"(b1));
}
__device__ __forceinline__ void cp16(uint32_t d, const void* s) {
    asm volatile("cp.async.cg.shared.global [%0], [%1], 16;" :: "r"(d), "l"(s) : "memory");
}
#define CP_COMMIT()  asm volatile("cp.async.commit_group;" ::: "memory")
#define CP_WAIT(n)   asm volatile("cp.async.wait_group %0;" :: "n"(n) : "memory")

// ---------------- RoPE + split ----------------
__device__ __forceinline__ void rope_pair(int p, int posT, int posH, int posW,
                                          float x0, float x1, float& o0, float& o1) {
    float fi, fdim, pp;
    if (p < 8)       { fi = (float)p;        fdim = 16.0f; pp = (float)posT; }
    else if (p < 36) { fi = (float)(p - 8);  fdim = 56.0f; pp = (float)posH; }
    else             { fi = (float)(p - 36); fdim = 56.0f; pp = (float)posW; }
    float freq = exp2f(-16.0f * fi / fdim);
    float s, c;
    sincosf(pp * freq, &s, &c);
    o0 = x0 * c - x1 * s;
    o1 = x1 * c + x0 * s;
}
__device__ __forceinline__ void splitbf(float x, bf16& hi, bf16& lo) {
    hi = __float2bfloat16_rn(x);
    lo = __float2bfloat16_rn(x - __bfloat162float(hi));
}

// ---------------- prep kernels ----------------
__global__ void prep_q_kernel(const float* __restrict__ qin) {
    int idx = blockIdx.x * blockDim.x + threadIdx.x;
    if (idx >= HEADS * NQB * BSZ * 64) return;
    int p  = idx & 63;
    int t  = (idx >> 6) & 255;
    int r  = idx >> 14;
    int qb = r % NQB, h = r / NQB;
    int qt = qb / 18, qh = (qb / 6) % 3, qw = qb % 6;
    int Tc = qt * 4 + (t >> 6), Hc = qh * 8 + ((t >> 3) & 7), Wc = qw * 8 + (t & 7);
    int pos = (Tc * 24 + Hc) * 48 + Wc;
    float2 x = *(const float2*)(qin + ((size_t)pos * HEADS + h) * HDIM + 2 * p);
    float o0, o1;
    rope_pair(p, Tc, Hc, Wc, x.x, x.y, o0, o1);
    o0 *= QK_SCALE; o1 *= QK_SCALE;
    bf16 h0, l0, h1, l1;
    splitbf(o0, h0, l0); splitbf(o1, h1, l1);
    *(__nv_bfloat162*)(g_Qhi + (size_t)idx * 2) = __halves2bfloat162(h0, h1);
    *(__nv_bfloat162*)(g_Qlo + (size_t)idx * 2) = __halves2bfloat162(l0, l1);
}

__global__ void prep_k_kernel(const float* __restrict__ kin) {
    int idx = blockIdx.x * blockDim.x + threadIdx.x;
    if (idx >= HEADS * NKVB * BSZ * 64) return;
    int p  = idx & 63;
    int t  = (idx >> 6) & 255;
    int r  = idx >> 14;
    int kb = r % NKVB, h = r / NKVB;
    int kt = kb / 40, kh = (kb >> 3) % 5, kw = kb & 7;
    int Tg = kt * 4 + (t >> 6);
    int Hg = kh * 8 + ((t >> 3) & 7);
    int Wg = kw * 8 + (t & 7);
    int Hc = (Hg + 16) % 24;
    int Wc = (Wg + 40) % 48;
    int pos = (Tg * 24 + Hc) * 48 + Wc;
    float2 x = *(const float2*)(kin + ((size_t)pos * HEADS + h) * HDIM + 2 * p);
    float o0, o1;
    rope_pair(p, Tg, Hg - 8, Wg - 8, x.x, x.y, o0, o1);
    bf16 h0, l0, h1, l1;
    splitbf(o0, h0, l0); splitbf(o1, h1, l1);
    *(__nv_bfloat162*)(g_Khi + (size_t)idx * 2) = __halves2bfloat162(h0, h1);
    *(__nv_bfloat162*)(g_Klo + (size_t)idx * 2) = __halves2bfloat162(l0, l1);
}

// V: glue only (no rope, no transpose). One thread per float4.
__global__ void prep_v_kernel(const float* __restrict__ vin) {
    int idx = blockIdx.x * blockDim.x + threadIdx.x;
    if (idx >= HEADS * NKVB * BSZ * 32) return;
    int e4 = idx & 31;
    int t  = (idx >> 5) & 255;
    int r  = idx >> 13;
    int kb = r % NKVB, h = r / NKVB;
    int kt = kb / 40, kh = (kb >> 3) % 5, kw = kb & 7;
    int Tg = kt * 4 + (t >> 6);
    int Hc = (kh * 8 + ((t >> 3) & 7) + 16) % 24;
    int Wc = (kw * 8 + (t & 7) + 40) % 48;
    int pos = (Tg * 24 + Hc) * 48 + Wc;
    float4 x = *(const float4*)(vin + ((size_t)pos * HEADS + h) * HDIM + e4 * 4);
    bf16 h0, l0, h1, l1, h2, l2, h3, l3;
    splitbf(x.x, h0, l0); splitbf(x.y, h1, l1);
    splitbf(x.z, h2, l2); splitbf(x.w, h3, l3);
    __nv_bfloat162 hA = __halves2bfloat162(h0, h1), hB = __halves2bfloat162(h2, h3);
    __nv_bfloat162 lA = __halves2bfloat162(l0, l1), lB = __halves2bfloat162(l2, l3);
    uint2 hu, lu;
    hu.x = *(uint32_t*)&hA; hu.y = *(uint32_t*)&hB;
    lu.x = *(uint32_t*)&lA; lu.y = *(uint32_t*)&lB;
    *(uint2*)(g_Vhi + (size_t)idx * 4) = hu;
    *(uint2*)(g_Vlo + (size_t)idx * 4) = lu;
}

// ---------------- smem layout ----------------
// buf0 @ 0, buf1 @ 65536 : each {KHI@0, KLO@16384, VHI@32768, VLO@49152}, 64 rows x 256B
// Qhi @ 131072, Qlo @ 163840 : 128 rows x 256B
#define SMEM_BYTES 196608

// swizzle: row t (256B = 16 chunks of 16B), chunk c -> ((c^t)&7)|(c&8)
__device__ __forceinline__ void issue_chunk(uint32_t sb, int bufsel,
                                            int h, int qh, int qw, int c, int tid) {
    int bi = c >> 2, toff = (c & 3) * 64;
    int kb = (bi / 9) * 40 + (qh + (bi / 3) % 3) * 8 + qw + (bi % 3);
    size_t base = ((size_t)(h * NKVB + kb) * BSZ + toff) * HDIM;
    uint32_t pc = (((((uint32_t)tid & 15) ^ (((uint32_t)tid >> 4) & 7)) & 7) | ((uint32_t)tid & 8)) * 16;
    uint32_t dbase = sb + bufsel * 65536 + ((tid >> 4) * 256) + pc;
    const bf16* srcs[4] = { g_Khi + base, g_Klo + base, g_Vhi + base, g_Vlo + base };
    #pragma unroll
    for (int arr = 0; arr < 4; arr++) {
        const char* s = (const char*)srcs[arr] + (size_t)tid * 16;
        uint32_t d = dbase + arr * 16384;
        #pragma unroll
        for (int jj = 0; jj < 4; jj++)
            cp16(d + jj * 4096, s + (size_t)jj * 4096);
    }
}

// ---------------- attention kernel (warp mma.sync, bf16 split) ----------------
__global__ void __launch_bounds__(256, 1)
attn_kernel(float* __restrict__ out) {
    extern __shared__ char sm[];
    uint32_t sb = smem_u32(sm);

    int bx = blockIdx.x;
    int h     = bx / 108;
    int rem   = bx % 108;
    int qhalf = rem / NQB;
    int qb    = rem % NQB;
    int qt = qb / 18, qh = (qb / 6) % 3, qw = qb % 6;

    int tid = threadIdx.x;
    int wid = tid >> 5, lane = tid & 31;
    int wm = wid * 16;
    int x = lane & 7;

    // ---- prologue: issue Q then chunk 0 ----
    {
        size_t qbase = ((size_t)(h * NQB + qb) * BSZ + qhalf * 128) * HDIM;
        uint32_t pc = (((((uint32_t)tid & 15) ^ (((uint32_t)tid >> 4) & 7)) & 7) | ((uint32_t)tid & 8)) * 16;
        uint32_t dbase = sb + 131072 + ((tid >> 4) * 256) + pc;
        const char* sh = (const char*)(g_Qhi + qbase) + (size_t)tid * 16;
        const char* sl = (const char*)(g_Qlo + qbase) + (size_t)tid * 16;
        #pragma unroll
        for (int jj = 0; jj < 8; jj++) {
            cp16(dbase + jj * 4096, sh + (size_t)jj * 4096);
            cp16(dbase + 32768 + jj * 4096, sl + (size_t)jj * 4096);
        }
        CP_COMMIT();
        issue_chunk(sb, 0, h, qh, qw, 0, tid);
        CP_COMMIT();
    }
    CP_WAIT(1);       // Q group done
    __syncthreads();

    // ---- Q fragments (persistent) ----
    uint32_t AH[8][4], AL[8][4];
    {
        int qr = (lane & 7) + ((lane >> 3) & 1) * 8;
        int qcs = (lane >> 4) & 1;
        #pragma unroll
        for (int s = 0; s < 8; s++) {
            int cQ = 2 * s + qcs;
            uint32_t off = ((((uint32_t)(cQ ^ x)) & 7) | ((uint32_t)cQ & 8)) * 16;
            uint32_t a = sb + 131072 + (wm + qr) * 256 + off;
            ldsm4(AH[s], a);
            ldsm4(AL[s], a + 32768);
        }
    }

    // ---- precomputed ldsm offsets ----
    uint32_t kOff[8], vOff[8];
    {
        int kcs = (lane >> 3) & 1;
        int vcs = (lane >> 4) & 1;
        #pragma unroll
        for (int s = 0; s < 8; s++) {
            int cK = 2 * s + kcs;
            kOff[s] = ((((uint32_t)(cK ^ x)) & 7) | ((uint32_t)cK & 8)) * 16;
            int cV = 2 * s + vcs;
            vOff[s] = ((((uint32_t)(cV ^ x)) & 7) | ((uint32_t)cV & 8)) * 16;
        }
    }
    uint32_t tokK = (uint32_t)(((lane & 7) + ((lane >> 4) & 1) * 8) * 256);
    uint32_t tokV = (uint32_t)((lane & 15) * 256);

    float O[16][4];
    #pragma unroll
    for (int n = 0; n < 16; n++)
        #pragma unroll
        for (int q = 0; q < 4; q++) O[n][q] = 0.0f;
    float ls0 = 0.0f, ls1 = 0.0f;

    for (int i = 0; i < NCH; i++) {
        int b = i & 1;
        uint32_t bufb = sb + b * 65536;

        if (i + 1 < NCH) {
            issue_chunk(sb, (i + 1) & 1, h, qh, qw, i + 1, tid);
            CP_COMMIT();
            CP_WAIT(1);
        } else {
            CP_WAIT(0);
        }
        __syncthreads();

        // ---- S = Q K^T (3-pass split) ----
        float S[8][4];
        #pragma unroll
        for (int n = 0; n < 8; n++)
            #pragma unroll
            for (int q = 0; q < 4; q++) S[n][q] = 0.0f;

        #pragma unroll
        for (int s = 0; s < 8; s++) {
            #pragma unroll
            for (int jp = 0; jp < 4; jp++) {
                uint32_t kb4[4];
                ldsm4(kb4, bufb + jp * 4096 + tokK + kOff[s]);
                mma_bf(S[2 * jp],     AH[s], kb4[0], kb4[1]);
                mma_bf(S[2 * jp + 1], AH[s], kb4[2], kb4[3]);
                mma_bf(S[2 * jp],     AL[s], kb4[0], kb4[1]);
                mma_bf(S[2 * jp + 1], AL[s], kb4[2], kb4[3]);
            }
            #pragma unroll
            for (int jp = 0; jp < 4; jp++) {
                uint32_t kb4[4];
                ldsm4(kb4, bufb + 16384 + jp * 4096 + tokK + kOff[s]);
                mma_bf(S[2 * jp],     AH[s], kb4[0], kb4[1]);
                mma_bf(S[2 * jp + 1], AH[s], kb4[2], kb4[3]);
            }
        }

        // ---- softmax (no max subtraction; scale folded into Q), P -> regs ----
        uint32_t PH[4][4], PL[4][4];
        #pragma unroll
        for (int n = 0; n < 8; n++) {
            float p0 = fast_exp2(S[n][0]);
            float p1 = fast_exp2(S[n][1]);
            float p2 = fast_exp2(S[n][2]);
            float p3 = fast_exp2(S[n][3]);
            ls0 += p0 + p1;
            ls1 += p2 + p3;
            __nv_bfloat162 hA = __floats2bfloat162_rn(p0, p1);
            __nv_bfloat162 hB = __floats2bfloat162_rn(p2, p3);
            uint32_t uhA = *(uint32_t*)&hA, uhB = *(uint32_t*)&hB;
            float fa0 = __uint_as_float(uhA << 16);
            float fa1 = __uint_as_float(uhA & 0xffff0000u);
            float fb0 = __uint_as_float(uhB << 16);
            float fb1 = __uint_as_float(uhB & 0xffff0000u);
            __nv_bfloat162 lA = __floats2bfloat162_rn(p0 - fa0, p1 - fa1);
            __nv_bfloat162 lB = __floats2bfloat162_rn(p2 - fb0, p3 - fb1);
            int srow = n >> 1, slot = (n & 1) * 2;
            PH[srow][slot]     = uhA;
            PH[srow][slot + 1] = uhB;
            PL[srow][slot]     = *(uint32_t*)&lA;
            PL[srow][slot + 1] = *(uint32_t*)&lB;
        }

        // ---- O += P V (3-pass split) ----
        #pragma unroll
        for (int s = 0; s < 4; s++) {
            #pragma unroll
            for (int jp = 0; jp < 8; jp++) {
                uint32_t vb[4];
                ldsm4t(vb, bufb + 32768 + s * 4096 + tokV + vOff[jp]);
                mma_bf(O[2 * jp],     PH[s], vb[0], vb[1]);
                mma_bf(O[2 * jp + 1], PH[s], vb[2], vb[3]);
                mma_bf(O[2 * jp],     PL[s], vb[0], vb[1]);
                mma_bf(O[2 * jp + 1], PL[s], vb[2], vb[3]);
            }
            #pragma unroll
            for (int jp = 0; jp < 8; jp++) {
                uint32_t vb[4];
                ldsm4t(vb, bufb + 49152 + s * 4096 + tokV + vOff[jp]);
                mma_bf(O[2 * jp],     PH[s], vb[0], vb[1]);
                mma_bf(O[2 * jp + 1], PH[s], vb[2], vb[3]);
            }
        }

        __syncthreads();   // all warps done with buffer b before it is refilled
    }

    // ---- epilogue: reduce l across quad, normalize, untile, write ----
    ls0 += __shfl_xor_sync(0xffffffffu, ls0, 1);
    ls0 += __shfl_xor_sync(0xffffffffu, ls0, 2);
    ls1 += __shfl_xor_sync(0xffffffffu, ls1, 1);
    ls1 += __shfl_xor_sync(0xffffffffu, ls1, 2);
    float inv0 = 1.0f / ls0, inv1 = 1.0f / ls1;

    int r0 = wm + (lane >> 2);
    int t0g = qhalf * 128 + r0;
    int t1g = t0g + 8;
    int a0 = t0g >> 6, a1 = (t0g >> 3) & 7, a2 = t0g & 7;
    int pos0 = ((qt * 4 + a0) * 24 + qh * 8 + a1) * 48 + (qw * 8 + a2);
    int b0_ = t1g >> 6, b1_ = (t1g >> 3) & 7, b2_ = t1g & 7;
    int pos1 = ((qt * 4 + b0_) * 24 + qh * 8 + b1_) * 48 + (qw * 8 + b2_);
    float* o0p = out + (size_t)pos0 * (HEADS * HDIM) + h * HDIM + (lane & 3) * 2;
    float* o1p = out + (size_t)pos1 * (HEADS * HDIM) + h * HDIM + (lane & 3) * 2;
    #pragma unroll
    for (int jn = 0; jn < 16; jn++) {
        *(float2*)(o0p + jn * 8) = make_float2(O[jn][0] * inv0, O[jn][1] * inv0);
        *(float2*)(o1p + jn * 8) = make_float2(O[jn][2] * inv1, O[jn][3] * inv1);
    }
}

// ---------------- launch ----------------
extern "C" void kernel_launch(void* const* d_in, const int* in_sizes, int n_in,
                              void* d_out, int out_size) {
    const float* q = (const float*)d_in[0];
    const float* k = (const float*)d_in[1];
    const float* v = (const float*)d_in[2];
    float* out = (float*)d_out;

    prep_q_kernel<<<(HEADS * NQB * BSZ * 64) / 256, 256>>>(q);
    prep_k_kernel<<<(HEADS * NKVB * BSZ * 64) / 256, 256>>>(k);
    prep_v_kernel<<<(HEADS * NKVB * BSZ * 32) / 256, 256>>>(v);

    cudaFuncSetAttribute(attn_kernel, cudaFuncAttributeMaxDynamicSharedMemorySize, SMEM_BYTES);
    attn_kernel<<<HEADS * 2 * NQB, 256, SMEM_BYTES>>>(out);
}

// round 14
// speedup vs baseline: 4.7844x; 2.2092x over previous
#include <cuda_runtime.h>
#include <cuda_bf16.h>
#include <cuda_fp16.h>
#include <cstdint>

// ---------------- problem constants ----------------
#define HEADS   24
#define HDIM    128
#define NQB     54
#define NKVB    120
#define BSZ     256
#define NCH     108                       // 27 blocks * 4 chunks of 64
#define QK_SCALE 0.127517443f             // (1/sqrt(128)) * log2(e), folded into Q

typedef __nv_bfloat16 bf16;

// ---------------- scratch (device globals; no cudaMalloc allowed) ----------
__device__ bf16   g_Qhi[(size_t)HEADS*NQB*BSZ*HDIM];    // [h][qb][t][e]
__device__ bf16   g_Qlo[(size_t)HEADS*NQB*BSZ*HDIM];
__device__ bf16   g_Khi[(size_t)HEADS*NKVB*BSZ*HDIM];   // [h][kb][t][e]
__device__ bf16   g_Klo[(size_t)HEADS*NKVB*BSZ*HDIM];
__device__ __half g_Vf [(size_t)HEADS*NKVB*BSZ*HDIM];   // [h][kb][t][e] fp16 single

// ---------------- PTX helpers (baseline ISA only) -------------
__device__ __forceinline__ uint32_t smem_u32(const void* p) {
    uint32_t a;
    asm("{ .reg .u64 t; cvta.to.shared.u64 t, %1; cvt.u32.u64 %0, t; }" : "=r"(a) : "l"(p));
    return a;
}
__device__ __forceinline__ float fast_exp2(float x) {
    float y; asm("ex2.approx.ftz.f32 %0, %1;" : "=f"(y) : "f"(x)); return y;
}
__device__ __forceinline__ void ldsm4(uint32_t r[4], uint32_t a) {
    asm volatile("ldmatrix.sync.aligned.m8n8.x4.shared.b16 {%0,%1,%2,%3}, [%4];"
        : "=r"(r[0]), "=r"(r[1]), "=r"(r[2]), "=r"(r[3]) : "r"(a));
}
__device__ __forceinline__ void ldsm4t(uint32_t r[4], uint32_t a) {
    asm volatile("ldmatrix.sync.aligned.m8n8.x4.trans.shared.b16 {%0,%1,%2,%3}, [%4];"
        : "=r"(r[0]), "=r"(r[1]), "=r"(r[2]), "=r"(r[3]) : "r"(a));
}
__device__ __forceinline__ void mma_bf(float c[4], const uint32_t a[4], uint32_t b0, uint32_t b1) {
    asm volatile("mma.sync.aligned.m16n8k16.row.col.f32.bf16.bf16.f32 "
        "{%0,%1,%2,%3}, {%4,%5,%6,%7}, {%8,%9}, {%0,%1,%2,%3};"
        : "+f"(c[0]), "+f"(c[1]), "+f"(c[2]), "+f"(c[3])
        : "r"(a[0]), "r"(a[1]), "r"(a[2]), "r"(a[3]), "r"(b0), "r"(b1));
}
__device__ __forceinline__ void mma_f16(float c[4], const uint32_t a[4], uint32_t b0, uint32_t b1) {
    asm volatile("mma.sync.aligned.m16n8k16.row.col.f32.f16.f16.f32 "
        "{%0,%1,%2,%3}, {%4,%5,%6,%7}, {%8,%9}, {%0,%1,%2,%3};"
        : "+f"(c[0]), "+f"(c[1]), "+f"(c[2]), "+f"(c[3])
        : "r"(a[0]), "r"(a[1]), "r"(a[2]), "r"(a[3]), "r"(b0), "r"(b1));
}
__device__ __forceinline__ void cp16(uint32_t d, const void* s) {
    asm volatile("cp.async.cg.shared.global [%0], [%1], 16;" :: "r"(d), "l"(s) : "memory");
}
#define CP_COMMIT()  asm volatile("cp.async.commit_group;" ::: "memory")
#define CP_WAIT(n)   asm volatile("cp.async.wait_group %0;" :: "n"(n) : "memory")

// ---------------- RoPE + split ----------------
__device__ __forceinline__ void rope_pair(int p, int posT, int posH, int posW,
                                          float x0, float x1, float& o0, float& o1) {
    float fi, fdim, pp;
    if (p < 8)       { fi = (float)p;        fdim = 16.0f; pp = (float)posT; }
    else if (p < 36) { fi = (float)(p - 8);  fdim = 56.0f; pp = (float)posH; }
    else             { fi = (float)(p - 36); fdim = 56.0f; pp = (float)posW; }
    float freq = exp2f(-16.0f * fi / fdim);
    float s, c;
    sincosf(pp * freq, &s, &c);
    o0 = x0 * c - x1 * s;
    o1 = x1 * c + x0 * s;
}
__device__ __forceinline__ void splitbf(float x, bf16& hi, bf16& lo) {
    hi = __float2bfloat16_rn(x);
    lo = __float2bfloat16_rn(x - __bfloat162float(hi));
}

// ---------------- prep kernels ----------------
__global__ void prep_q_kernel(const float* __restrict__ qin) {
    int idx = blockIdx.x * blockDim.x + threadIdx.x;
    if (idx >= HEADS * NQB * BSZ * 64) return;
    int p  = idx & 63;
    int t  = (idx >> 6) & 255;
    int r  = idx >> 14;
    int qb = r % NQB, h = r / NQB;
    int qt = qb / 18, qh = (qb / 6) % 3, qw = qb % 6;
    int Tc = qt * 4 + (t >> 6), Hc = qh * 8 + ((t >> 3) & 7), Wc = qw * 8 + (t & 7);
    int pos = (Tc * 24 + Hc) * 48 + Wc;
    float2 x = *(const float2*)(qin + ((size_t)pos * HEADS + h) * HDIM + 2 * p);
    float o0, o1;
    rope_pair(p, Tc, Hc, Wc, x.x, x.y, o0, o1);
    o0 *= QK_SCALE; o1 *= QK_SCALE;
    bf16 h0, l0, h1, l1;
    splitbf(o0, h0, l0); splitbf(o1, h1, l1);
    *(__nv_bfloat162*)(g_Qhi + (size_t)idx * 2) = __halves2bfloat162(h0, h1);
    *(__nv_bfloat162*)(g_Qlo + (size_t)idx * 2) = __halves2bfloat162(l0, l1);
}

__global__ void prep_k_kernel(const float* __restrict__ kin) {
    int idx = blockIdx.x * blockDim.x + threadIdx.x;
    if (idx >= HEADS * NKVB * BSZ * 64) return;
    int p  = idx & 63;
    int t  = (idx >> 6) & 255;
    int r  = idx >> 14;
    int kb = r % NKVB, h = r / NKVB;
    int kt = kb / 40, kh = (kb >> 3) % 5, kw = kb & 7;
    int Tg = kt * 4 + (t >> 6);
    int Hg = kh * 8 + ((t >> 3) & 7);
    int Wg = kw * 8 + (t & 7);
    int Hc = (Hg + 16) % 24;
    int Wc = (Wg + 40) % 48;
    int pos = (Tg * 24 + Hc) * 48 + Wc;
    float2 x = *(const float2*)(kin + ((size_t)pos * HEADS + h) * HDIM + 2 * p);
    float o0, o1;
    rope_pair(p, Tg, Hg - 8, Wg - 8, x.x, x.y, o0, o1);
    bf16 h0, l0, h1, l1;
    splitbf(o0, h0, l0); splitbf(o1, h1, l1);
    *(__nv_bfloat162*)(g_Khi + (size_t)idx * 2) = __halves2bfloat162(h0, h1);
    *(__nv_bfloat162*)(g_Klo + (size_t)idx * 2) = __halves2bfloat162(l0, l1);
}

// V: glue + fp16 convert. One thread per float4.
__global__ void prep_v_kernel(const float* __restrict__ vin) {
    int idx = blockIdx.x * blockDim.x + threadIdx.x;
    if (idx >= HEADS * NKVB * BSZ * 32) return;
    int e4 = idx & 31;
    int t  = (idx >> 5) & 255;
    int r  = idx >> 13;
    int kb = r % NKVB, h = r / NKVB;
    int kt = kb / 40, kh = (kb >> 3) % 5, kw = kb & 7;
    int Tg = kt * 4 + (t >> 6);
    int Hc = (kh * 8 + ((t >> 3) & 7) + 16) % 24;
    int Wc = (kw * 8 + (t & 7) + 40) % 48;
    int pos = (Tg * 24 + Hc) * 48 + Wc;
    float4 x = *(const float4*)(vin + ((size_t)pos * HEADS + h) * HDIM + e4 * 4);
    __half2 a = __floats2half2_rn(x.x, x.y);
    __half2 b = __floats2half2_rn(x.z, x.w);
    uint2 u;
    u.x = *(uint32_t*)&a; u.y = *(uint32_t*)&b;
    *(uint2*)(g_Vf + (size_t)idx * 4) = u;
}

// ---------------- smem layout ----------------
// buf b @ b*49152 : {KHI@0, KLO@16384, VF@32768}, each 64 rows x 256B
// Qhi @ 98304, Qlo @ 131072 : 128 rows x 256B
#define BUF_STRIDE 49152
#define VOFF       32768
#define QOFF       98304
#define SMEM_BYTES 163840

// swizzle: row t (256B = 16 chunks of 16B), chunk c -> ((c^t)&7)|(c&8)
__device__ __forceinline__ void issue_chunk(uint32_t sb, int bufsel,
                                            int h, int qh, int qw, int c, int tid) {
    int bi = c >> 2, toff = (c & 3) * 64;
    int kb = (bi / 9) * 40 + (qh + (bi / 3) % 3) * 8 + qw + (bi % 3);
    size_t base = ((size_t)(h * NKVB + kb) * BSZ + toff) * HDIM;
    uint32_t pc = (((((uint32_t)tid & 15) ^ (((uint32_t)tid >> 4) & 7)) & 7) | ((uint32_t)tid & 8)) * 16;
    uint32_t dbase = sb + bufsel * BUF_STRIDE + ((tid >> 4) * 256) + pc;
    const char* sK0 = (const char*)(g_Khi + base) + (size_t)tid * 16;
    const char* sK1 = (const char*)(g_Klo + base) + (size_t)tid * 16;
    const char* sV  = (const char*)(g_Vf  + base) + (size_t)tid * 16;
    #pragma unroll
    for (int jj = 0; jj < 4; jj++) {
        cp16(dbase + jj * 4096,             sK0 + (size_t)jj * 4096);
        cp16(dbase + 16384 + jj * 4096,     sK1 + (size_t)jj * 4096);
        cp16(dbase + VOFF + jj * 4096,      sV  + (size_t)jj * 4096);
    }
}

// ---------------- attention kernel (warp mma.sync) ----------------
__global__ void __launch_bounds__(256, 1)
attn_kernel(float* __restrict__ out) {
    extern __shared__ char sm[];
    uint32_t sb = smem_u32(sm);

    int bx = blockIdx.x;
    int h     = bx / 108;
    int rem   = bx % 108;
    int qhalf = rem / NQB;
    int qb    = rem % NQB;
    int qt = qb / 18, qh = (qb / 6) % 3, qw = qb % 6;

    int tid = threadIdx.x;
    int wid = tid >> 5, lane = tid & 31;
    int wm = wid * 16;
    int x = lane & 7;

    // ---- prologue: issue Q then chunk 0 ----
    {
        size_t qbase = ((size_t)(h * NQB + qb) * BSZ + qhalf * 128) * HDIM;
        uint32_t pc = (((((uint32_t)tid & 15) ^ (((uint32_t)tid >> 4) & 7)) & 7) | ((uint32_t)tid & 8)) * 16;
        uint32_t dbase = sb + QOFF + ((tid >> 4) * 256) + pc;
        const char* sh = (const char*)(g_Qhi + qbase) + (size_t)tid * 16;
        const char* sl = (const char*)(g_Qlo + qbase) + (size_t)tid * 16;
        #pragma unroll
        for (int jj = 0; jj < 8; jj++) {
            cp16(dbase + jj * 4096, sh + (size_t)jj * 4096);
            cp16(dbase + 32768 + jj * 4096, sl + (size_t)jj * 4096);
        }
        CP_COMMIT();
        issue_chunk(sb, 0, h, qh, qw, 0, tid);
        CP_COMMIT();
    }
    CP_WAIT(1);       // Q group done
    __syncthreads();

    // ---- Q fragments (persistent) ----
    uint32_t AH[8][4], AL[8][4];
    {
        int qr = (lane & 7) + ((lane >> 3) & 1) * 8;
        int qcs = (lane >> 4) & 1;
        #pragma unroll
        for (int s = 0; s < 8; s++) {
            int cQ = 2 * s + qcs;
            uint32_t off = ((((uint32_t)(cQ ^ x)) & 7) | ((uint32_t)cQ & 8)) * 16;
            uint32_t a = sb + QOFF + (wm + qr) * 256 + off;
            ldsm4(AH[s], a);
            ldsm4(AL[s], a + 32768);
        }
    }

    // ---- precomputed ldsm offsets ----
    uint32_t kOff[8], vOff[8];
    {
        int kcs = (lane >> 3) & 1;
        int vcs = (lane >> 4) & 1;
        #pragma unroll
        for (int s = 0; s < 8; s++) {
            int cK = 2 * s + kcs;
            kOff[s] = ((((uint32_t)(cK ^ x)) & 7) | ((uint32_t)cK & 8)) * 16;
            int cV = 2 * s + vcs;
            vOff[s] = ((((uint32_t)(cV ^ x)) & 7) | ((uint32_t)cV & 8)) * 16;
        }
    }
    uint32_t tokK = (uint32_t)(((lane & 7) + ((lane >> 4) & 1) * 8) * 256);
    uint32_t tokV = (uint32_t)((lane & 15) * 256);

    float O[16][4];
    #pragma unroll
    for (int n = 0; n < 16; n++)
        #pragma unroll
        for (int q = 0; q < 4; q++) O[n][q] = 0.0f;
    float ls0 = 0.0f, ls1 = 0.0f;

    for (int i = 0; i < NCH; i++) {
        int b = i & 1;
        uint32_t bufb = sb + b * BUF_STRIDE;

        if (i + 1 < NCH) {
            issue_chunk(sb, (i + 1) & 1, h, qh, qw, i + 1, tid);
            CP_COMMIT();
            CP_WAIT(1);
        } else {
            CP_WAIT(0);
        }
        __syncthreads();

        // ---- S = Q K^T (3-pass bf16 split) ----
        float S[8][4];
        #pragma unroll
        for (int n = 0; n < 8; n++)
            #pragma unroll
            for (int q = 0; q < 4; q++) S[n][q] = 0.0f;

        #pragma unroll
        for (int s = 0; s < 8; s++) {
            #pragma unroll
            for (int jp = 0; jp < 4; jp++) {
                uint32_t kb4[4];
                ldsm4(kb4, bufb + jp * 4096 + tokK + kOff[s]);
                mma_bf(S[2 * jp],     AH[s], kb4[0], kb4[1]);
                mma_bf(S[2 * jp + 1], AH[s], kb4[2], kb4[3]);
                mma_bf(S[2 * jp],     AL[s], kb4[0], kb4[1]);
                mma_bf(S[2 * jp + 1], AL[s], kb4[2], kb4[3]);
            }
            #pragma unroll
            for (int jp = 0; jp < 4; jp++) {
                uint32_t kb4[4];
                ldsm4(kb4, bufb + 16384 + jp * 4096 + tokK + kOff[s]);
                mma_bf(S[2 * jp],     AH[s], kb4[0], kb4[1]);
                mma_bf(S[2 * jp + 1], AH[s], kb4[2], kb4[3]);
            }
        }

        // ---- softmax (no max subtraction; scale folded into Q), P -> fp16 regs ----
        uint32_t PH[4][4];
        #pragma unroll
        for (int n = 0; n < 8; n++) {
            float p0 = fast_exp2(S[n][0]);
            float p1 = fast_exp2(S[n][1]);
            float p2 = fast_exp2(S[n][2]);
            float p3 = fast_exp2(S[n][3]);
            ls0 += p0 + p1;
            ls1 += p2 + p3;
            __half2 hA = __floats2half2_rn(p0, p1);
            __half2 hB = __floats2half2_rn(p2, p3);
            int srow = n >> 1, slot = (n & 1) * 2;
            PH[srow][slot]     = *(uint32_t*)&hA;
            PH[srow][slot + 1] = *(uint32_t*)&hB;
        }

        // ---- O += P V (single-pass fp16) ----
        #pragma unroll
        for (int s = 0; s < 4; s++) {
            #pragma unroll
            for (int jp = 0; jp < 8; jp++) {
                uint32_t vb[4];
                ldsm4t(vb, bufb + VOFF + s * 4096 + tokV + vOff[jp]);
                mma_f16(O[2 * jp],     PH[s], vb[0], vb[1]);
                mma_f16(O[2 * jp + 1], PH[s], vb[2], vb[3]);
            }
        }

        __syncthreads();   // all warps done with buffer b before it is refilled
    }

    // ---- epilogue: reduce l across quad, normalize, untile, write ----
    ls0 += __shfl_xor_sync(0xffffffffu, ls0, 1);
    ls0 += __shfl_xor_sync(0xffffffffu, ls0, 2);
    ls1 += __shfl_xor_sync(0xffffffffu, ls1, 1);
    ls1 += __shfl_xor_sync(0xffffffffu, ls1, 2);
    float inv0 = 1.0f / ls0, inv1 = 1.0f / ls1;

    int r0 = wm + (lane >> 2);
    int t0g = qhalf * 128 + r0;
    int t1g = t0g + 8;
    int a0 = t0g >> 6, a1 = (t0g >> 3) & 7, a2 = t0g & 7;
    int pos0 = ((qt * 4 + a0) * 24 + qh * 8 + a1) * 48 + (qw * 8 + a2);
    int b0_ = t1g >> 6, b1_ = (t1g >> 3) & 7, b2_ = t1g & 7;
    int pos1 = ((qt * 4 + b0_) * 24 + qh * 8 + b1_) * 48 + (qw * 8 + b2_);
    float* o0p = out + (size_t)pos0 * (HEADS * HDIM) + h * HDIM + (lane & 3) * 2;
    float* o1p = out + (size_t)pos1 * (HEADS * HDIM) + h * HDIM + (lane & 3) * 2;
    #pragma unroll
    for (int jn = 0; jn < 16; jn++) {
        *(float2*)(o0p + jn * 8) = make_float2(O[jn][0] * inv0, O[jn][1] * inv0);
        *(float2*)(o1p + jn * 8) = make_float2(O[jn][2] * inv1, O[jn][3] * inv1);
    }
}

// ---------------- launch ----------------
extern "C" void kernel_launch(void* const* d_in, const int* in_sizes, int n_in,
                              void* d_out, int out_size) {
    const float* q = (const float*)d_in[0];
    const float* k = (const float*)d_in[1];
    const float* v = (const float*)d_in[2];
    float* out = (float*)d_out;

    prep_q_kernel<<<(HEADS * NQB * BSZ * 64) / 256, 256>>>(q);
    prep_k_kernel<<<(HEADS * NKVB * BSZ * 64) / 256, 256>>>(k);
    prep_v_kernel<<<(HEADS * NKVB * BSZ * 32) / 256, 256>>>(v);

    cudaFuncSetAttribute(attn_kernel, cudaFuncAttributeMaxDynamicSharedMemorySize, SMEM_BYTES);
    attn_kernel<<<HEADS * 2 * NQB, 256, SMEM_BYTES>>>(out);
}

// round 15
// speedup vs baseline: 7.7692x; 1.6238x over previous
#include <cuda_runtime.h>
#include <cuda_fp16.h>
#include <cstdint>

// ---------------- problem constants ----------------
#define HEADS   24
#define HDIM    128
#define NQB     54
#define NKVB    120
#define BSZ     256
#define NCH     108                       // 27 blocks * 4 chunks of 64
#define QK_SCALE 0.127517443f             // (1/sqrt(128)) * log2(e), folded into Q

// ---------------- scratch (device globals; no cudaMalloc allowed) ----------
__device__ __half g_Qf[(size_t)HEADS*NQB*BSZ*HDIM];    // [h][qb][t][e] fp16 (scaled)
__device__ __half g_Kf[(size_t)HEADS*NKVB*BSZ*HDIM];   // [h][kb][t][e] fp16
__device__ __half g_Vf[(size_t)HEADS*NKVB*BSZ*HDIM];   // [h][kb][t][e] fp16

// ---------------- PTX helpers (baseline ISA only) -------------
__device__ __forceinline__ uint32_t smem_u32(const void* p) {
    uint32_t a;
    asm("{ .reg .u64 t; cvta.to.shared.u64 t, %1; cvt.u32.u64 %0, t; }" : "=r"(a) : "l"(p));
    return a;
}
__device__ __forceinline__ float fast_exp2(float x) {
    float y; asm("ex2.approx.ftz.f32 %0, %1;" : "=f"(y) : "f"(x)); return y;
}
__device__ __forceinline__ void ldsm4(uint32_t r[4], uint32_t a) {
    asm volatile("ldmatrix.sync.aligned.m8n8.x4.shared.b16 {%0,%1,%2,%3}, [%4];"
        : "=r"(r[0]), "=r"(r[1]), "=r"(r[2]), "=r"(r[3]) : "r"(a));
}
__device__ __forceinline__ void ldsm4t(uint32_t r[4], uint32_t a) {
    asm volatile("ldmatrix.sync.aligned.m8n8.x4.trans.shared.b16 {%0,%1,%2,%3}, [%4];"
        : "=r"(r[0]), "=r"(r[1]), "=r"(r[2]), "=r"(r[3]) : "r"(a));
}
__device__ __forceinline__ void mma_f16(float c[4], const uint32_t a[4], uint32_t b0, uint32_t b1) {
    asm volatile("mma.sync.aligned.m16n8k16.row.col.f32.f16.f16.f32 "
        "{%0,%1,%2,%3}, {%4,%5,%6,%7}, {%8,%9}, {%0,%1,%2,%3};"
        : "+f"(c[0]), "+f"(c[1]), "+f"(c[2]), "+f"(c[3])
        : "r"(a[0]), "r"(a[1]), "r"(a[2]), "r"(a[3]), "r"(b0), "r"(b1));
}
__device__ __forceinline__ void cp16(uint32_t d, const void* s) {
    asm volatile("cp.async.cg.shared.global [%0], [%1], 16;" :: "r"(d), "l"(s) : "memory");
}
#define CP_COMMIT()  asm volatile("cp.async.commit_group;" ::: "memory")
#define CP_WAIT(n)   asm volatile("cp.async.wait_group %0;" :: "n"(n) : "memory")

// ---------------- RoPE ----------------
__device__ __forceinline__ void rope_pair(int p, int posT, int posH, int posW,
                                          float x0, float x1, float& o0, float& o1) {
    float fi, fdim, pp;
    if (p < 8)       { fi = (float)p;        fdim = 16.0f; pp = (float)posT; }
    else if (p < 36) { fi = (float)(p - 8);  fdim = 56.0f; pp = (float)posH; }
    else             { fi = (float)(p - 36); fdim = 56.0f; pp = (float)posW; }
    float freq = exp2f(-16.0f * fi / fdim);
    float s, c;
    sincosf(pp * freq, &s, &c);
    o0 = x0 * c - x1 * s;
    o1 = x1 * c + x0 * s;
}

// ---------------- prep kernels ----------------
__global__ void prep_q_kernel(const float* __restrict__ qin) {
    int idx = blockIdx.x * blockDim.x + threadIdx.x;
    if (idx >= HEADS * NQB * BSZ * 64) return;
    int p  = idx & 63;
    int t  = (idx >> 6) & 255;
    int r  = idx >> 14;
    int qb = r % NQB, h = r / NQB;
    int qt = qb / 18, qh = (qb / 6) % 3, qw = qb % 6;
    int Tc = qt * 4 + (t >> 6), Hc = qh * 8 + ((t >> 3) & 7), Wc = qw * 8 + (t & 7);
    int pos = (Tc * 24 + Hc) * 48 + Wc;
    float2 x = *(const float2*)(qin + ((size_t)pos * HEADS + h) * HDIM + 2 * p);
    float o0, o1;
    rope_pair(p, Tc, Hc, Wc, x.x, x.y, o0, o1);
    __half2 v = __floats2half2_rn(o0 * QK_SCALE, o1 * QK_SCALE);
    *(__half2*)(g_Qf + (size_t)idx * 2) = v;
}

__global__ void prep_k_kernel(const float* __restrict__ kin) {
    int idx = blockIdx.x * blockDim.x + threadIdx.x;
    if (idx >= HEADS * NKVB * BSZ * 64) return;
    int p  = idx & 63;
    int t  = (idx >> 6) & 255;
    int r  = idx >> 14;
    int kb = r % NKVB, h = r / NKVB;
    int kt = kb / 40, kh = (kb >> 3) % 5, kw = kb & 7;
    int Tg = kt * 4 + (t >> 6);
    int Hg = kh * 8 + ((t >> 3) & 7);
    int Wg = kw * 8 + (t & 7);
    int Hc = (Hg + 16) % 24;
    int Wc = (Wg + 40) % 48;
    int pos = (Tg * 24 + Hc) * 48 + Wc;
    float2 x = *(const float2*)(kin + ((size_t)pos * HEADS + h) * HDIM + 2 * p);
    float o0, o1;
    rope_pair(p, Tg, Hg - 8, Wg - 8, x.x, x.y, o0, o1);
    __half2 v = __floats2half2_rn(o0, o1);
    *(__half2*)(g_Kf + (size_t)idx * 2) = v;
}

// V: glue + fp16 convert. One thread per float4.
__global__ void prep_v_kernel(const float* __restrict__ vin) {
    int idx = blockIdx.x * blockDim.x + threadIdx.x;
    if (idx >= HEADS * NKVB * BSZ * 32) return;
    int e4 = idx & 31;
    int t  = (idx >> 5) & 255;
    int r  = idx >> 13;
    int kb = r % NKVB, h = r / NKVB;
    int kt = kb / 40, kh = (kb >> 3) % 5, kw = kb & 7;
    int Tg = kt * 4 + (t >> 6);
    int Hc = (kh * 8 + ((t >> 3) & 7) + 16) % 24;
    int Wc = (kw * 8 + (t & 7) + 40) % 48;
    int pos = (Tg * 24 + Hc) * 48 + Wc;
    float4 x = *(const float4*)(vin + ((size_t)pos * HEADS + h) * HDIM + e4 * 4);
    __half2 a = __floats2half2_rn(x.x, x.y);
    __half2 b = __floats2half2_rn(x.z, x.w);
    uint2 u;
    u.x = *(uint32_t*)&a; u.y = *(uint32_t*)&b;
    *(uint2*)(g_Vf + (size_t)idx * 4) = u;
}

// ---------------- smem layout ----------------
// buf b @ b*32768 : {KF@0, VF@16384}, each 64 rows x 256B
// Qf @ 65536 : 128 rows x 256B
#define BUF_STRIDE 32768
#define VOFF       16384
#define QOFF       65536
#define SMEM_BYTES 98304

// swizzle: row t (256B = 16 chunks of 16B), chunk c -> ((c^t)&7)|(c&8)
__device__ __forceinline__ void issue_chunk(uint32_t sb, int bufsel,
                                            int h, int qh, int qw, int c, int tid) {
    int bi = c >> 2, toff = (c & 3) * 64;
    int kb = (bi / 9) * 40 + (qh + (bi / 3) % 3) * 8 + qw + (bi % 3);
    size_t base = ((size_t)(h * NKVB + kb) * BSZ + toff) * HDIM;
    uint32_t pc = (((((uint32_t)tid & 15) ^ (((uint32_t)tid >> 4) & 7)) & 7) | ((uint32_t)tid & 8)) * 16;
    uint32_t dbase = sb + bufsel * BUF_STRIDE + ((tid >> 4) * 256) + pc;
    const char* sK = (const char*)(g_Kf + base) + (size_t)tid * 16;
    const char* sV = (const char*)(g_Vf + base) + (size_t)tid * 16;
    #pragma unroll
    for (int jj = 0; jj < 4; jj++) {
        cp16(dbase + jj * 4096,        sK + (size_t)jj * 4096);
        cp16(dbase + VOFF + jj * 4096, sV + (size_t)jj * 4096);
    }
}

// ---------------- attention kernel (warp mma.sync, fp16) ----------------
__global__ void __launch_bounds__(256, 1)
attn_kernel(float* __restrict__ out) {
    extern __shared__ char sm[];
    uint32_t sb = smem_u32(sm);

    int bx = blockIdx.x;
    int h     = bx / 108;
    int rem   = bx % 108;
    int qhalf = rem / NQB;
    int qb    = rem % NQB;
    int qt = qb / 18, qh = (qb / 6) % 3, qw = qb % 6;

    int tid = threadIdx.x;
    int wid = tid >> 5, lane = tid & 31;
    int wm = wid * 16;
    int x = lane & 7;

    // ---- prologue: issue Q then chunk 0 ----
    {
        size_t qbase = ((size_t)(h * NQB + qb) * BSZ + qhalf * 128) * HDIM;
        uint32_t pc = (((((uint32_t)tid & 15) ^ (((uint32_t)tid >> 4) & 7)) & 7) | ((uint32_t)tid & 8)) * 16;
        uint32_t dbase = sb + QOFF + ((tid >> 4) * 256) + pc;
        const char* sq = (const char*)(g_Qf + qbase) + (size_t)tid * 16;
        #pragma unroll
        for (int jj = 0; jj < 8; jj++)
            cp16(dbase + jj * 4096, sq + (size_t)jj * 4096);
        CP_COMMIT();
        issue_chunk(sb, 0, h, qh, qw, 0, tid);
        CP_COMMIT();
    }
    CP_WAIT(1);       // Q group done
    __syncthreads();

    // ---- Q fragments (persistent) ----
    uint32_t AH[8][4];
    {
        int qr = (lane & 7) + ((lane >> 3) & 1) * 8;
        int qcs = (lane >> 4) & 1;
        #pragma unroll
        for (int s = 0; s < 8; s++) {
            int cQ = 2 * s + qcs;
            uint32_t off = ((((uint32_t)(cQ ^ x)) & 7) | ((uint32_t)cQ & 8)) * 16;
            ldsm4(AH[s], sb + QOFF + (wm + qr) * 256 + off);
        }
    }

    // ---- precomputed ldsm offsets ----
    uint32_t kOff[8], vOff[8];
    {
        int kcs = (lane >> 3) & 1;
        int vcs = (lane >> 4) & 1;
        #pragma unroll
        for (int s = 0; s < 8; s++) {
            int cK = 2 * s + kcs;
            kOff[s] = ((((uint32_t)(cK ^ x)) & 7) | ((uint32_t)cK & 8)) * 16;
            int cV = 2 * s + vcs;
            vOff[s] = ((((uint32_t)(cV ^ x)) & 7) | ((uint32_t)cV & 8)) * 16;
        }
    }
    uint32_t tokK = (uint32_t)(((lane & 7) + ((lane >> 4) & 1) * 8) * 256);
    uint32_t tokV = (uint32_t)((lane & 15) * 256);

    float O[16][4];
    #pragma unroll
    for (int n = 0; n < 16; n++)
        #pragma unroll
        for (int q = 0; q < 4; q++) O[n][q] = 0.0f;
    float ls0 = 0.0f, ls1 = 0.0f;

    for (int i = 0; i < NCH; i++) {
        int b = i & 1;
        uint32_t bufb = sb + b * BUF_STRIDE;

        if (i + 1 < NCH) {
            issue_chunk(sb, (i + 1) & 1, h, qh, qw, i + 1, tid);
            CP_COMMIT();
            CP_WAIT(1);
        } else {
            CP_WAIT(0);
        }
        __syncthreads();

        // ---- S = Q K^T (single-pass fp16) ----
        float S[8][4];
        #pragma unroll
        for (int n = 0; n < 8; n++)
            #pragma unroll
            for (int q = 0; q < 4; q++) S[n][q] = 0.0f;

        #pragma unroll
        for (int s = 0; s < 8; s++) {
            #pragma unroll
            for (int jp = 0; jp < 4; jp++) {
                uint32_t kb4[4];
                ldsm4(kb4, bufb + jp * 4096 + tokK + kOff[s]);
                mma_f16(S[2 * jp],     AH[s], kb4[0], kb4[1]);
                mma_f16(S[2 * jp + 1], AH[s], kb4[2], kb4[3]);
            }
        }

        // ---- softmax (no max subtraction; scale folded into Q), P -> fp16 regs ----
        uint32_t PH[4][4];
        #pragma unroll
        for (int n = 0; n < 8; n++) {
            float p0 = fast_exp2(S[n][0]);
            float p1 = fast_exp2(S[n][1]);
            float p2 = fast_exp2(S[n][2]);
            float p3 = fast_exp2(S[n][3]);
            ls0 += p0 + p1;
            ls1 += p2 + p3;
            __half2 hA = __floats2half2_rn(p0, p1);
            __half2 hB = __floats2half2_rn(p2, p3);
            int srow = n >> 1, slot = (n & 1) * 2;
            PH[srow][slot]     = *(uint32_t*)&hA;
            PH[srow][slot + 1] = *(uint32_t*)&hB;
        }

        // ---- O += P V (single-pass fp16) ----
        #pragma unroll
        for (int s = 0; s < 4; s++) {
            #pragma unroll
            for (int jp = 0; jp < 8; jp++) {
                uint32_t vb[4];
                ldsm4t(vb, bufb + VOFF + s * 4096 + tokV + vOff[jp]);
                mma_f16(O[2 * jp],     PH[s], vb[0], vb[1]);
                mma_f16(O[2 * jp + 1], PH[s], vb[2], vb[3]);
            }
        }

        __syncthreads();   // all warps done with buffer b before it is refilled
    }

    // ---- epilogue: reduce l across quad, normalize, untile, write ----
    ls0 += __shfl_xor_sync(0xffffffffu, ls0, 1);
    ls0 += __shfl_xor_sync(0xffffffffu, ls0, 2);
    ls1 += __shfl_xor_sync(0xffffffffu, ls1, 1);
    ls1 += __shfl_xor_sync(0xffffffffu, ls1, 2);
    float inv0 = 1.0f / ls0, inv1 = 1.0f / ls1;

    int r0 = wm + (lane >> 2);
    int t0g = qhalf * 128 + r0;
    int t1g = t0g + 8;
    int a0 = t0g >> 6, a1 = (t0g >> 3) & 7, a2 = t0g & 7;
    int pos0 = ((qt * 4 + a0) * 24 + qh * 8 + a1) * 48 + (qw * 8 + a2);
    int b0_ = t1g >> 6, b1_ = (t1g >> 3) & 7, b2_ = t1g & 7;
    int pos1 = ((qt * 4 + b0_) * 24 + qh * 8 + b1_) * 48 + (qw * 8 + b2_);
    float* o0p = out + (size_t)pos0 * (HEADS * HDIM) + h * HDIM + (lane & 3) * 2;
    float* o1p = out + (size_t)pos1 * (HEADS * HDIM) + h * HDIM + (lane & 3) * 2;
    #pragma unroll
    for (int jn = 0; jn < 16; jn++) {
        *(float2*)(o0p + jn * 8) = make_float2(O[jn][0] * inv0, O[jn][1] * inv0);
        *(float2*)(o1p + jn * 8) = make_float2(O[jn][2] * inv1, O[jn][3] * inv1);
    }
}

// ---------------- launch ----------------
extern "C" void kernel_launch(void* const* d_in, const int* in_sizes, int n_in,
                              void* d_out, int out_size) {
    const float* q = (const float*)d_in[0];
    const float* k = (const float*)d_in[1];
    const float* v = (const float*)d_in[2];
    float* out = (float*)d_out;

    prep_q_kernel<<<(HEADS * NQB * BSZ * 64) / 256, 256>>>(q);
    prep_k_kernel<<<(HEADS * NKVB * BSZ * 64) / 256, 256>>>(k);
    prep_v_kernel<<<(HEADS * NKVB * BSZ * 32) / 256, 256>>>(v);

    cudaFuncSetAttribute(attn_kernel, cudaFuncAttributeMaxDynamicSharedMemorySize, SMEM_BYTES);
    attn_kernel<<<HEADS * 2 * NQB, 256, SMEM_BYTES>>>(out);
}

// round 16
// speedup vs baseline: 8.3533x; 1.0752x over previous
#include <cuda_runtime.h>
#include <cuda_fp16.h>
#include <cstdint>

// ---------------- problem constants ----------------
#define HEADS   24
#define HDIM    128
#define NQB     54
#define NKVB    120
#define BSZ     256
#define NCH     108                       // 27 blocks * 4 chunks of 64
#define QK_SCALE 0.127517443f             // (1/sqrt(128)) * log2(e), folded into Q

// ---------------- scratch (device globals; no cudaMalloc allowed) ----------
__device__ __half g_Qf[(size_t)HEADS*NQB*BSZ*HDIM];    // [h][qb][t][e] fp16 (scaled)
__device__ __half g_Kf[(size_t)HEADS*NKVB*BSZ*HDIM];   // [h][kb][t][e] fp16
__device__ __half g_Vf[(size_t)HEADS*NKVB*BSZ*HDIM];   // [h][kb][t][e] fp16

// ---------------- PTX helpers (baseline ISA only) -------------
__device__ __forceinline__ uint32_t smem_u32(const void* p) {
    uint32_t a;
    asm("{ .reg .u64 t; cvta.to.shared.u64 t, %1; cvt.u32.u64 %0, t; }" : "=r"(a) : "l"(p));
    return a;
}
__device__ __forceinline__ float fast_exp2(float x) {
    float y; asm("ex2.approx.ftz.f32 %0, %1;" : "=f"(y) : "f"(x)); return y;
}
__device__ __forceinline__ void ldsm4(uint32_t r[4], uint32_t a) {
    asm volatile("ldmatrix.sync.aligned.m8n8.x4.shared.b16 {%0,%1,%2,%3}, [%4];"
        : "=r"(r[0]), "=r"(r[1]), "=r"(r[2]), "=r"(r[3]) : "r"(a));
}
__device__ __forceinline__ void ldsm4t(uint32_t r[4], uint32_t a) {
    asm volatile("ldmatrix.sync.aligned.m8n8.x4.trans.shared.b16 {%0,%1,%2,%3}, [%4];"
        : "=r"(r[0]), "=r"(r[1]), "=r"(r[2]), "=r"(r[3]) : "r"(a));
}
__device__ __forceinline__ void mma_f16(float c[4], const uint32_t a[4], uint32_t b0, uint32_t b1) {
    asm volatile("mma.sync.aligned.m16n8k16.row.col.f32.f16.f16.f32 "
        "{%0,%1,%2,%3}, {%4,%5,%6,%7}, {%8,%9}, {%0,%1,%2,%3};"
        : "+f"(c[0]), "+f"(c[1]), "+f"(c[2]), "+f"(c[3])
        : "r"(a[0]), "r"(a[1]), "r"(a[2]), "r"(a[3]), "r"(b0), "r"(b1));
}
__device__ __forceinline__ void cp16(uint32_t d, const void* s) {
    asm volatile("cp.async.cg.shared.global [%0], [%1], 16;" :: "r"(d), "l"(s) : "memory");
}
#define CP_COMMIT()  asm volatile("cp.async.commit_group;" ::: "memory")
#define CP_WAIT(n)   asm volatile("cp.async.wait_group %0;" :: "n"(n) : "memory")

// ---------------- RoPE ----------------
__device__ __forceinline__ void rope_pair(int p, int posT, int posH, int posW,
                                          float x0, float x1, float& o0, float& o1) {
    float fi, fdim, pp;
    if (p < 8)       { fi = (float)p;        fdim = 16.0f; pp = (float)posT; }
    else if (p < 36) { fi = (float)(p - 8);  fdim = 56.0f; pp = (float)posH; }
    else             { fi = (float)(p - 36); fdim = 56.0f; pp = (float)posW; }
    float freq = exp2f(-16.0f * fi / fdim);
    float s, c;
    sincosf(pp * freq, &s, &c);
    o0 = x0 * c - x1 * s;
    o1 = x1 * c + x0 * s;
}

// ---------------- prep kernels ----------------
__global__ void prep_q_kernel(const float* __restrict__ qin) {
    int idx = blockIdx.x * blockDim.x + threadIdx.x;
    if (idx >= HEADS * NQB * BSZ * 64) return;
    int p  = idx & 63;
    int t  = (idx >> 6) & 255;
    int r  = idx >> 14;
    int qb = r % NQB, h = r / NQB;
    int qt = qb / 18, qh = (qb / 6) % 3, qw = qb % 6;
    int Tc = qt * 4 + (t >> 6), Hc = qh * 8 + ((t >> 3) & 7), Wc = qw * 8 + (t & 7);
    int pos = (Tc * 24 + Hc) * 48 + Wc;
    float2 x = *(const float2*)(qin + ((size_t)pos * HEADS + h) * HDIM + 2 * p);
    float o0, o1;
    rope_pair(p, Tc, Hc, Wc, x.x, x.y, o0, o1);
    __half2 v = __floats2half2_rn(o0 * QK_SCALE, o1 * QK_SCALE);
    *(__half2*)(g_Qf + (size_t)idx * 2) = v;
}

__global__ void prep_k_kernel(const float* __restrict__ kin) {
    int idx = blockIdx.x * blockDim.x + threadIdx.x;
    if (idx >= HEADS * NKVB * BSZ * 64) return;
    int p  = idx & 63;
    int t  = (idx >> 6) & 255;
    int r  = idx >> 14;
    int kb = r % NKVB, h = r / NKVB;
    int kt = kb / 40, kh = (kb >> 3) % 5, kw = kb & 7;
    int Tg = kt * 4 + (t >> 6);
    int Hg = kh * 8 + ((t >> 3) & 7);
    int Wg = kw * 8 + (t & 7);
    int Hc = (Hg + 16) % 24;
    int Wc = (Wg + 40) % 48;
    int pos = (Tg * 24 + Hc) * 48 + Wc;
    float2 x = *(const float2*)(kin + ((size_t)pos * HEADS + h) * HDIM + 2 * p);
    float o0, o1;
    rope_pair(p, Tg, Hg - 8, Wg - 8, x.x, x.y, o0, o1);
    __half2 v = __floats2half2_rn(o0, o1);
    *(__half2*)(g_Kf + (size_t)idx * 2) = v;
}

// V: glue + fp16 convert. One thread per float4.
__global__ void prep_v_kernel(const float* __restrict__ vin) {
    int idx = blockIdx.x * blockDim.x + threadIdx.x;
    if (idx >= HEADS * NKVB * BSZ * 32) return;
    int e4 = idx & 31;
    int t  = (idx >> 5) & 255;
    int r  = idx >> 13;
    int kb = r % NKVB, h = r / NKVB;
    int kt = kb / 40, kh = (kb >> 3) % 5, kw = kb & 7;
    int Tg = kt * 4 + (t >> 6);
    int Hc = (kh * 8 + ((t >> 3) & 7) + 16) % 24;
    int Wc = (kw * 8 + (t & 7) + 40) % 48;
    int pos = (Tg * 24 + Hc) * 48 + Wc;
    float4 x = *(const float4*)(vin + ((size_t)pos * HEADS + h) * HDIM + e4 * 4);
    __half2 a = __floats2half2_rn(x.x, x.y);
    __half2 b = __floats2half2_rn(x.z, x.w);
    uint2 u;
    u.x = *(uint32_t*)&a; u.y = *(uint32_t*)&b;
    *(uint2*)(g_Vf + (size_t)idx * 4) = u;
}

// ---------------- smem layout ----------------
// buf b @ b*32768 : {KF@0, VF@16384}, each 64 rows x 256B
// Qf @ 65536 : 256 rows x 256B (full q block)
#define BUF_STRIDE 32768
#define VOFF       16384
#define QOFF       65536
#define SMEM_BYTES 131072

// swizzle: row t (256B = 16 chunks of 16B), chunk c -> ((c^t)&7)|(c&8)
__device__ __forceinline__ void issue_chunk(uint32_t sb, int bufsel,
                                            int h, int qh, int qw, int c, int tid) {
    int bi = c >> 2, toff = (c & 3) * 64;
    int kb = (bi / 9) * 40 + (qh + (bi / 3) % 3) * 8 + qw + (bi % 3);
    size_t base = ((size_t)(h * NKVB + kb) * BSZ + toff) * HDIM;
    uint32_t pc = (((((uint32_t)tid & 15) ^ (((uint32_t)tid >> 4) & 7)) & 7) | ((uint32_t)tid & 8)) * 16;
    uint32_t dbase = sb + bufsel * BUF_STRIDE + ((tid >> 4) * 256) + pc;
    const char* sK = (const char*)(g_Kf + base) + (size_t)tid * 16;
    const char* sV = (const char*)(g_Vf + base) + (size_t)tid * 16;
    #pragma unroll
    for (int jj = 0; jj < 4; jj++) {
        cp16(dbase + jj * 4096,        sK + (size_t)jj * 4096);
        cp16(dbase + VOFF + jj * 4096, sV + (size_t)jj * 4096);
    }
}

// ---------------- attention kernel: m32/warp, full 256-row q block per CTA ----
__global__ void __launch_bounds__(256, 1)
attn_kernel(float* __restrict__ out) {
    extern __shared__ char sm[];
    uint32_t sb = smem_u32(sm);

    int bx = blockIdx.x;
    int h  = bx / NQB;
    int qb = bx % NQB;
    int qt = qb / 18, qh = (qb / 6) % 3, qw = qb % 6;

    int tid = threadIdx.x;
    int wid = tid >> 5, lane = tid & 31;
    int wm2 = wid * 32;                  // 32 q rows per warp
    int x = lane & 7;

    // ---- prologue: issue Q (full 256 rows) then chunk 0 ----
    {
        size_t qbase = (size_t)(h * NQB + qb) * BSZ * HDIM;
        uint32_t pc = (((((uint32_t)tid & 15) ^ (((uint32_t)tid >> 4) & 7)) & 7) | ((uint32_t)tid & 8)) * 16;
        uint32_t dbase = sb + QOFF + ((tid >> 4) * 256) + pc;
        const char* sq = (const char*)(g_Qf + qbase) + (size_t)tid * 16;
        #pragma unroll
        for (int jj = 0; jj < 16; jj++)
            cp16(dbase + jj * 4096, sq + (size_t)jj * 4096);
        CP_COMMIT();
        issue_chunk(sb, 0, h, qh, qw, 0, tid);
        CP_COMMIT();
    }

    // ---- precomputed ldsm offsets ----
    int qr = (lane & 7) + ((lane >> 3) & 1) * 8;
    uint32_t qOff[8], kOff[8], vOff[8];
    {
        int qcs = (lane >> 4) & 1;
        int kcs = (lane >> 3) & 1;
        int vcs = (lane >> 4) & 1;
        #pragma unroll
        for (int s = 0; s < 8; s++) {
            int cQ = 2 * s + qcs;
            qOff[s] = ((((uint32_t)(cQ ^ x)) & 7) | ((uint32_t)cQ & 8)) * 16;
            int cK = 2 * s + kcs;
            kOff[s] = ((((uint32_t)(cK ^ x)) & 7) | ((uint32_t)cK & 8)) * 16;
            int cV = 2 * s + vcs;
            vOff[s] = ((((uint32_t)(cV ^ x)) & 7) | ((uint32_t)cV & 8)) * 16;
        }
    }
    uint32_t tokK = (uint32_t)(((lane & 7) + ((lane >> 4) & 1) * 8) * 256);
    uint32_t tokV = (uint32_t)((lane & 15) * 256);
    uint32_t qrowA = sb + QOFF + (uint32_t)((wm2 + qr) * 256);       // mtile 0
    uint32_t qrowB = qrowA + 16 * 256;                                // mtile 1

    float O[2][16][4];
    #pragma unroll
    for (int mt = 0; mt < 2; mt++)
        #pragma unroll
        for (int n = 0; n < 16; n++)
            #pragma unroll
            for (int q = 0; q < 4; q++) O[mt][n][q] = 0.0f;
    float ls[4] = {0.f, 0.f, 0.f, 0.f};

    CP_WAIT(1);       // Q group done
    __syncthreads();

    for (int i = 0; i < NCH; i++) {
        int b = i & 1;
        uint32_t bufb = sb + b * BUF_STRIDE;

        if (i + 1 < NCH) {
            issue_chunk(sb, (i + 1) & 1, h, qh, qw, i + 1, tid);
            CP_COMMIT();
            CP_WAIT(1);
        } else {
            CP_WAIT(0);
        }
        __syncthreads();

        // ---- S = Q K^T : m32 x kv64, Q streamed from smem ----
        float S[2][8][4];
        #pragma unroll
        for (int mt = 0; mt < 2; mt++)
            #pragma unroll
            for (int n = 0; n < 8; n++)
                #pragma unroll
                for (int q = 0; q < 4; q++) S[mt][n][q] = 0.0f;

        #pragma unroll
        for (int s = 0; s < 8; s++) {
            uint32_t q0[4], q1[4];
            ldsm4(q0, qrowA + qOff[s]);
            ldsm4(q1, qrowB + qOff[s]);
            #pragma unroll
            for (int jp = 0; jp < 4; jp++) {
                uint32_t kb4[4];
                ldsm4(kb4, bufb + jp * 4096 + tokK + kOff[s]);
                mma_f16(S[0][2 * jp],     q0, kb4[0], kb4[1]);
                mma_f16(S[0][2 * jp + 1], q0, kb4[2], kb4[3]);
                mma_f16(S[1][2 * jp],     q1, kb4[0], kb4[1]);
                mma_f16(S[1][2 * jp + 1], q1, kb4[2], kb4[3]);
            }
        }

        // ---- softmax (scale folded into Q), P -> fp16 regs ----
        uint32_t PH[2][4][4];
        #pragma unroll
        for (int mt = 0; mt < 2; mt++) {
            #pragma unroll
            for (int n = 0; n < 8; n++) {
                float p0 = fast_exp2(S[mt][n][0]);
                float p1 = fast_exp2(S[mt][n][1]);
                float p2 = fast_exp2(S[mt][n][2]);
                float p3 = fast_exp2(S[mt][n][3]);
                ls[mt * 2]     += p0 + p1;
                ls[mt * 2 + 1] += p2 + p3;
                __half2 hA = __floats2half2_rn(p0, p1);
                __half2 hB = __floats2half2_rn(p2, p3);
                int srow = n >> 1, slot = (n & 1) * 2;
                PH[mt][srow][slot]     = *(uint32_t*)&hA;
                PH[mt][srow][slot + 1] = *(uint32_t*)&hB;
            }
        }

        // ---- O += P V : m32 x e128 ----
        #pragma unroll
        for (int s = 0; s < 4; s++) {
            #pragma unroll
            for (int jp = 0; jp < 8; jp++) {
                uint32_t vb[4];
                ldsm4t(vb, bufb + VOFF + s * 4096 + tokV + vOff[jp]);
                mma_f16(O[0][2 * jp],     PH[0][s], vb[0], vb[1]);
                mma_f16(O[0][2 * jp + 1], PH[0][s], vb[2], vb[3]);
                mma_f16(O[1][2 * jp],     PH[1][s], vb[0], vb[1]);
                mma_f16(O[1][2 * jp + 1], PH[1][s], vb[2], vb[3]);
            }
        }

        __syncthreads();   // all warps done with buffer b before it is refilled
    }

    // ---- epilogue: reduce l across quad, normalize, untile, write ----
    #pragma unroll
    for (int i = 0; i < 4; i++) {
        ls[i] += __shfl_xor_sync(0xffffffffu, ls[i], 1);
        ls[i] += __shfl_xor_sync(0xffffffffu, ls[i], 2);
    }
    #pragma unroll
    for (int i = 0; i < 4; i++) {
        int mt = i >> 1, rsel = i & 1;
        float iv = 1.0f / ls[i];
        int t = wm2 + mt * 16 + rsel * 8 + (lane >> 2);
        int t0 = t >> 6, t1 = (t >> 3) & 7, t2 = t & 7;
        int pos = ((qt * 4 + t0) * 24 + qh * 8 + t1) * 48 + (qw * 8 + t2);
        float* op = out + (size_t)pos * (HEADS * HDIM) + h * HDIM + (lane & 3) * 2;
        int qsel = rsel * 2;
        #pragma unroll
        for (int nt = 0; nt < 16; nt++) {
            *(float2*)(op + nt * 8) =
                make_float2(O[mt][nt][qsel] * iv, O[mt][nt][qsel + 1] * iv);
        }
    }
}

// ---------------- launch ----------------
extern "C" void kernel_launch(void* const* d_in, const int* in_sizes, int n_in,
                              void* d_out, int out_size) {
    const float* q = (const float*)d_in[0];
    const float* k = (const float*)d_in[1];
    const float* v = (const float*)d_in[2];
    float* out = (float*)d_out;

    prep_q_kernel<<<(HEADS * NQB * BSZ * 64) / 256, 256>>>(q);
    prep_k_kernel<<<(HEADS * NKVB * BSZ * 64) / 256, 256>>>(k);
    prep_v_kernel<<<(HEADS * NKVB * BSZ * 32) / 256, 256>>>(v);

    cudaFuncSetAttribute(attn_kernel, cudaFuncAttributeMaxDynamicSharedMemorySize, SMEM_BYTES);
    attn_kernel<<<HEADS * NQB, 256, SMEM_BYTES>>>(out);
}